// round 5
// baseline (speedup 1.0000x reference)
#include <cuda_runtime.h>
#include <math.h>

// Problem constants
#define BB    2
#define HH    256
#define WWd   256
#define CC    180
#define WS_   8
#define OWS_  12
#define NH_   6
#define HD    30      // CC/NH
#define C4    720     // 4*CC
#define HD4   120     // 4*HD
#define NPIX  131072  // BB*HH*WWd
#define HPIX  32768   // BB*128*128
#define NWIN  512     // BB*16*16
#define NQ    64
#define NKV   144

// ------------------------- scratch (device globals) -------------------------
__device__ float g_xn[23592960];   // LN1 out (B,256,256,180); reused for LN2 out
__device__ float g_xd[23592960];   // DWT out (B,128,128,720); reused for xr
__device__ float g_q [5898240];    // (B,128,128,180)
__device__ float g_k [5898240];    // (B,128,128,180)
__device__ float g_v [23592960];   // (B,128,128,720)
__device__ float g_o [23592960];   // (512,64,720)
__device__ float g_h1[47185920];   // (131072,360)
__device__ float g_bias[55296];    // (6,64,144)

// ------------------------- LayerNorm: one warp per row ----------------------
__global__ void ln_kernel(const float* __restrict__ x, const float* __restrict__ w,
                          const float* __restrict__ b, float* __restrict__ y, int rows)
{
    int warp = (blockIdx.x * blockDim.x + threadIdx.x) >> 5;
    int lane = threadIdx.x & 31;
    if (warp >= rows) return;
    const float* xr = x + (size_t)warp * CC;
    float vals[6];
    float sum = 0.f;
#pragma unroll
    for (int i = 0; i < 6; i++) {
        int idx = lane + 32 * i;
        vals[i] = (idx < CC) ? xr[idx] : 0.f;
        sum += vals[i];
    }
#pragma unroll
    for (int o = 16; o > 0; o >>= 1) sum += __shfl_xor_sync(0xffffffffu, sum, o);
    float mean = sum * (1.f / CC);
    float vs = 0.f;
#pragma unroll
    for (int i = 0; i < 6; i++) {
        int idx = lane + 32 * i;
        if (idx < CC) { float d = vals[i] - mean; vs += d * d; }
    }
#pragma unroll
    for (int o = 16; o > 0; o >>= 1) vs += __shfl_xor_sync(0xffffffffu, vs, o);
    float rstd = rsqrtf(vs * (1.f / CC) + 1e-5f);
    float* yr = y + (size_t)warp * CC;
#pragma unroll
    for (int i = 0; i < 6; i++) {
        int idx = lane + 32 * i;
        if (idx < CC) yr[idx] = (vals[i] - mean) * rstd * w[idx] + b[idx];
    }
}

// ------------------------- DWT2: (B,256,256,180) -> (B,128,128,720) ---------
__global__ void dwt_kernel()
{
    int idx = blockIdx.x * blockDim.x + threadIdx.x;
    if (idx >= HPIX * C4) return;
    int c4  = idx % C4;
    int pix = idx / C4;
    int x2  = pix % 128;
    int y2  = (pix / 128) % 128;
    int bi  = pix / (128 * 128);
    int band = c4 / CC;
    int c    = c4 % CC;
    size_t base = (((size_t)bi * 256 + 2 * y2) * 256 + 2 * x2) * CC + c;
    float a  = g_xn[base];
    float bq = g_xn[base + CC];
    float cq = g_xn[base + 256 * CC];
    float dq = g_xn[base + 256 * CC + CC];
    float v;
    if      (band == 0) v = ( a + bq + cq + dq);
    else if (band == 1) v = (-a - bq + cq + dq);
    else if (band == 2) v = (-a + bq - cq + dq);
    else                v = ( a - bq - cq + dq);
    g_xd[idx] = v * 0.5f;
}

// ------------------------- IDWT2: g_o (512,64,720) -> g_xd as xr ------------
__global__ void idwt_kernel()
{
    int idx = blockIdx.x * blockDim.x + threadIdx.x;
    if (idx >= NPIX * CC) return;
    int c   = idx % CC;
    int pix = idx / CC;
    int x   = pix % 256;
    int y   = (pix / 256) % 256;
    int bi  = pix / (256 * 256);
    int hy = y >> 1, hx = x >> 1;
    int win = bi * 256 + (hy >> 3) * 16 + (hx >> 3);
    int qq  = (hy & 7) * 8 + (hx & 7);
    const float* p = g_o + ((size_t)win * NQ + qq) * C4 + c;
    float ll = p[0], lh = p[CC], hl = p[2 * CC], hh = p[3 * CC];
    int py = y & 1, px = x & 1;
    float v;
    if      (py == 0 && px == 0) v = (ll - lh - hl + hh);
    else if (py == 0 && px == 1) v = (ll - lh + hl - hh);
    else if (py == 1 && px == 0) v = (ll + lh - hl - hh);
    else                         v = (ll + lh + hl + hh);
    g_xd[idx] = v * 0.5f;
}

// ------------------------- generic tiled SGEMM with epilogue ----------------
// C[M,N] = epi(A[M,K] @ W[K,N] + bias[N]) (+ res[M,N])
// epi: 0 = identity, 1 = exact GELU
#define BM 64
#define BN 64
#define BK 16
__global__ void sgemm_kernel(const float* __restrict__ A, const float* __restrict__ W,
                             const float* __restrict__ bias, const float* __restrict__ res,
                             float* __restrict__ C, int M, int N, int K, int gelu)
{
    __shared__ float As[BK][BM + 4];
    __shared__ float Ws[BK][BN];
    int tid = threadIdx.x;
    int tx = tid & 15, ty = tid >> 4;
    int row0 = blockIdx.y * BM, col0 = blockIdx.x * BN;
    float acc[4][4];
#pragma unroll
    for (int i = 0; i < 4; i++)
#pragma unroll
        for (int j = 0; j < 4; j++) acc[i][j] = 0.f;

    for (int k0 = 0; k0 < K; k0 += BK) {
#pragma unroll
        for (int i = tid; i < BM * BK; i += 256) {
            int r = i >> 4, c = i & 15;  // BK=16
            float v = 0.f;
            if (row0 + r < M && k0 + c < K) v = A[(size_t)(row0 + r) * K + k0 + c];
            As[c][r] = v;
        }
#pragma unroll
        for (int i = tid; i < BK * BN; i += 256) {
            int r = i >> 6, c = i & 63;  // BN=64
            float v = 0.f;
            if (col0 + c < N && k0 + r < K) v = W[(size_t)(k0 + r) * N + col0 + c];
            Ws[r][c] = v;
        }
        __syncthreads();
#pragma unroll
        for (int kk = 0; kk < BK; kk++) {
            float ra[4], rb[4];
#pragma unroll
            for (int i = 0; i < 4; i++) ra[i] = As[kk][ty * 4 + i];
#pragma unroll
            for (int j = 0; j < 4; j++) rb[j] = Ws[kk][tx * 4 + j];
#pragma unroll
            for (int i = 0; i < 4; i++)
#pragma unroll
                for (int j = 0; j < 4; j++) acc[i][j] += ra[i] * rb[j];
        }
        __syncthreads();
    }
#pragma unroll
    for (int i = 0; i < 4; i++) {
        int row = row0 + ty * 4 + i;
        if (row >= M) continue;
#pragma unroll
        for (int j = 0; j < 4; j++) {
            int col = col0 + tx * 4 + j;
            if (col >= N) continue;
            float v = acc[i][j] + bias[col];
            if (gelu) v = 0.5f * v * (1.f + erff(v * 0.70710678118654752f));
            if (res) v += res[(size_t)row * N + col];
            C[(size_t)row * N + col] = v;
        }
    }
}

// ------------------------- relative position bias gather --------------------
__global__ void bias_kernel(const int* __restrict__ rpi, const float* __restrict__ rpb)
{
    int idx = blockIdx.x * blockDim.x + threadIdx.x;
    if (idx >= NH_ * NQ * NKV) return;
    int h = idx / (NQ * NKV);
    int r = (idx / NKV) % NQ;
    int n = idx % NKV;
    g_bias[idx] = rpb[rpi[r * NKV + n] * NH_ + h];
}

// ------------------------- attention: one block per (window, head) ----------
// smem: qs[64*30] | ks[144*30] (reused for v chunks) | s[64*144]
#define SMEM_ATTN ((NQ * HD + NKV * HD + NQ * NKV) * 4)
__global__ void attn_kernel()
{
    extern __shared__ float sm[];
    float* qs = sm;                       // 1920
    float* ks = sm + NQ * HD;             // 4320
    float* s  = sm + NQ * HD + NKV * HD;  // 9216

    int win = blockIdx.x;
    int hh  = blockIdx.y;
    int tid = threadIdx.x;
    int bi = win / 256;
    int rem = win % 256;
    int wy = rem / 16, wx = rem % 16;
    const float scale = 0.18257418583505536f;  // 30^-0.5

    // load q (scaled)
    for (int i = tid; i < NQ * HD; i += 256) {
        int qq = i / HD, d = i % HD;
        int y = wy * 8 + (qq >> 3), x = wx * 8 + (qq & 7);
        size_t pix = ((size_t)bi * 128 + y) * 128 + x;
        qs[i] = g_q[pix * CC + hh * HD + d] * scale;
    }
    // load k (zero-padded window)
    for (int i = tid; i < NKV * HD; i += 256) {
        int n = i / HD, d = i % HD;
        int y = wy * 8 + n / 12 - 4, x = wx * 8 + n % 12 - 4;
        float v = 0.f;
        if (y >= 0 && y < 128 && x >= 0 && x < 128) {
            size_t pix = ((size_t)bi * 128 + y) * 128 + x;
            v = g_k[pix * CC + hh * HD + d];
        }
        ks[i] = v;
    }
    __syncthreads();

    // scores + bias
    for (int i = tid; i < NQ * NKV; i += 256) {
        int qq = i / NKV, n = i % NKV;
        float acc = g_bias[(hh * NQ + qq) * NKV + n];
        const float* qp = qs + qq * HD;
        const float* kp = ks + n * HD;
#pragma unroll
        for (int d = 0; d < HD; d++) acc += qp[d] * kp[d];
        s[i] = acc;
    }
    __syncthreads();

    // softmax: 8 warps x 8 rows
    {
        int warp = tid >> 5, lane = tid & 31;
        for (int r = warp * 8; r < warp * 8 + 8; r++) {
            float* row = s + r * NKV;
            float m = -1e30f;
            for (int n = lane; n < NKV; n += 32) m = fmaxf(m, row[n]);
#pragma unroll
            for (int o = 16; o > 0; o >>= 1) m = fmaxf(m, __shfl_xor_sync(0xffffffffu, m, o));
            float sum = 0.f;
            for (int n = lane; n < NKV; n += 32) {
                float e = __expf(row[n] - m);
                row[n] = e;
                sum += e;
            }
#pragma unroll
            for (int o = 16; o > 0; o >>= 1) sum += __shfl_xor_sync(0xffffffffu, sum, o);
            float inv = 1.f / sum;
            for (int n = lane; n < NKV; n += 32) row[n] *= inv;
        }
    }
    __syncthreads();

    // P @ V, in 4 chunks of 30 output dims (reuse ks for v chunk)
    for (int c0 = 0; c0 < HD4; c0 += HD) {
        for (int i = tid; i < NKV * HD; i += 256) {
            int n = i / HD, d = i % HD;
            int y = wy * 8 + n / 12 - 4, x = wx * 8 + n % 12 - 4;
            float v = 0.f;
            if (y >= 0 && y < 128 && x >= 0 && x < 128) {
                size_t pix = ((size_t)bi * 128 + y) * 128 + x;
                v = g_v[pix * C4 + hh * HD4 + c0 + d];
            }
            ks[i] = v;
        }
        __syncthreads();
        for (int i = tid; i < NQ * HD; i += 256) {
            int qq = i / HD, d = i % HD;
            const float* sp = s + qq * NKV;
            float acc = 0.f;
#pragma unroll 4
            for (int n = 0; n < NKV; n++) acc += sp[n] * ks[n * HD + d];
            g_o[((size_t)win * NQ + qq) * C4 + hh * HD4 + c0 + d] = acc;
        }
        __syncthreads();
    }
}

// ------------------------- launcher -----------------------------------------
extern "C" void kernel_launch(void* const* d_in, const int* in_sizes, int n_in,
                              void* d_out, int out_size)
{
    const float* x       = (const float*)d_in[0];
    const int*   rpi     = (const int*)  d_in[2];
    const float* norm1_w = (const float*)d_in[5];
    const float* norm1_b = (const float*)d_in[6];
    const float* q_w     = (const float*)d_in[9];
    const float* q_b     = (const float*)d_in[10];
    const float* k_w     = (const float*)d_in[11];
    const float* k_b     = (const float*)d_in[12];
    const float* v_w     = (const float*)d_in[13];
    const float* v_b     = (const float*)d_in[14];
    const float* rpb     = (const float*)d_in[15];
    const float* proj_w  = (const float*)d_in[16];
    const float* proj_b  = (const float*)d_in[17];
    const float* norm2_w = (const float*)d_in[18];
    const float* norm2_b = (const float*)d_in[19];
    const float* fc1_w   = (const float*)d_in[20];
    const float* fc1_b   = (const float*)d_in[21];
    const float* fc2_w   = (const float*)d_in[22];
    const float* fc2_b   = (const float*)d_in[23];
    float* out = (float*)d_out;

    void *p_xn, *p_xd, *p_q, *p_k, *p_v, *p_h1;
    cudaGetSymbolAddress(&p_xn, g_xn);
    cudaGetSymbolAddress(&p_xd, g_xd);
    cudaGetSymbolAddress(&p_q,  g_q);
    cudaGetSymbolAddress(&p_k,  g_k);
    cudaGetSymbolAddress(&p_v,  g_v);
    cudaGetSymbolAddress(&p_h1, g_h1);
    float* xn = (float*)p_xn;
    float* xd = (float*)p_xd;
    float* qf = (float*)p_q;
    float* kf = (float*)p_k;
    float* vf = (float*)p_v;
    float* h1 = (float*)p_h1;

    cudaFuncSetAttribute(attn_kernel, cudaFuncAttributeMaxDynamicSharedMemorySize, SMEM_ATTN);

    // 1. LN1
    ln_kernel<<<NPIX / 8, 256>>>(x, norm1_w, norm1_b, xn, NPIX);
    // 2. DWT
    dwt_kernel<<<(HPIX * C4 + 255) / 256, 256>>>();
    // 3-5. Q,K,V projections
    {
        dim3 gq((CC + BN - 1) / BN, HPIX / BM);
        sgemm_kernel<<<gq, 256>>>(xd, q_w, q_b, nullptr, qf, HPIX, CC, C4, 0);
        sgemm_kernel<<<gq, 256>>>(xd, k_w, k_b, nullptr, kf, HPIX, CC, C4, 0);
        dim3 gv((C4 + BN - 1) / BN, HPIX / BM);
        sgemm_kernel<<<gv, 256>>>(xd, v_w, v_b, nullptr, vf, HPIX, C4, C4, 0);
    }
    // 6. rel-pos bias table
    bias_kernel<<<(NH_ * NQ * NKV + 255) / 256, 256>>>(rpi, rpb);
    // 7. attention
    {
        dim3 g(NWIN, NH_);
        attn_kernel<<<g, 256, SMEM_ATTN>>>();
    }
    // 8. IDWT (xr -> g_xd, reuse)
    idwt_kernel<<<(NPIX * CC + 255) / 256, 256>>>();
    // 9. proj + residual -> out (x1)
    {
        dim3 g((CC + BN - 1) / BN, NPIX / BM);
        sgemm_kernel<<<g, 256>>>(xd, proj_w, proj_b, x, out, NPIX, CC, CC, 0);
    }
    // 10. LN2 (x1 -> g_xn, reuse)
    ln_kernel<<<NPIX / 8, 256>>>(out, norm2_w, norm2_b, xn, NPIX);
    // 11. fc1 + GELU
    {
        dim3 g((2 * CC + BN - 1) / BN, NPIX / BM);
        sgemm_kernel<<<g, 256>>>(xn, fc1_w, fc1_b, nullptr, h1, NPIX, 2 * CC, CC, 1);
    }
    // 12. fc2 + residual(x1) -> out
    {
        dim3 g((CC + BN - 1) / BN, NPIX / BM);
        sgemm_kernel<<<g, 256>>>(h1, fc2_w, fc2_b, out, out, NPIX, CC, 2 * CC, 0);
    }
}

// round 8
// speedup vs baseline: 2.2879x; 2.2879x over previous
#include <cuda_runtime.h>
#include <cuda_bf16.h>
#include <math.h>
#include <stdint.h>

// Problem constants
#define BB    2
#define HH    256
#define WWd   256
#define CC    180
#define NH_   6
#define HD    30      // CC/NH
#define C4    720     // 4*CC
#define HD4   120     // 4*HD
#define NPIX  131072  // BB*HH*WWd
#define HPIX  32768   // BB*128*128
#define NWIN  512     // BB*16*16
#define NQ    64
#define NKV   144

// Padded dims (K -> mult of 64, N -> mult of 128 tiles)
#define KP_XD   768   // 720 -> 768
#define KP_180  192   // 180 -> 192
#define KP_360  384   // 360 -> 384

#define SLOTB   25165824   // 32768*768 == 131072*192

// ------------------------- scratch (device globals) -------------------------
__device__ float g_xn[23592960];           // LN1 out (B,256,256,180)
__device__ float g_q [5898240];            // (B,128,128,180)
__device__ float g_k [5898240];            // (B,128,128,180)
__device__ float g_v [23592960];           // (B,128,128,720)
__device__ float g_o [23592960];           // (512,64,720)
__device__ float g_bias[55296];            // (6,64,144)
__device__ __nv_bfloat16 g_ah[75497472];   // activations hi (slotA + slotB)
__device__ __nv_bfloat16 g_al[75497472];   // activations lo
__device__ __nv_bfloat16 g_wh[1228800];    // weights hi (transposed, padded)
__device__ __nv_bfloat16 g_wl[1228800];    // weights lo

// weight pool offsets (rows x Kp)
#define WOFF_Q    0         // 256 x 768
#define WOFF_K    196608    // 256 x 768
#define WOFF_V    393216    // 768 x 768
#define WOFF_PROJ 983040    // 256 x 192
#define WOFF_FC1  1032192   // 512 x 192
#define WOFF_FC2  1130496   // 256 x 384

// ------------------------- helpers ------------------------------------------
__device__ __forceinline__ uint32_t smem_u32(const void* p) {
    uint32_t a;
    asm("{ .reg .u64 t; cvta.to.shared.u64 t, %1; cvt.u32.u64 %0, t; }" : "=r"(a) : "l"(p));
    return a;
}
__device__ __forceinline__ void ldm_x4(uint32_t& r0, uint32_t& r1, uint32_t& r2, uint32_t& r3,
                                       uint32_t addr) {
    asm volatile("ldmatrix.sync.aligned.m8n8.x4.shared.b16 {%0,%1,%2,%3}, [%4];"
        : "=r"(r0), "=r"(r1), "=r"(r2), "=r"(r3) : "r"(addr));
}
__device__ __forceinline__ void ldm_x2(uint32_t& r0, uint32_t& r1, uint32_t addr) {
    asm volatile("ldmatrix.sync.aligned.m8n8.x2.shared.b16 {%0,%1}, [%2];"
        : "=r"(r0), "=r"(r1) : "r"(addr));
}
__device__ __forceinline__ void mma_bf16(float* c, const uint32_t* a, const uint32_t* b) {
    asm volatile("mma.sync.aligned.m16n8k16.row.col.f32.bf16.bf16.f32 "
        "{%0,%1,%2,%3}, {%4,%5,%6,%7}, {%8,%9}, {%0,%1,%2,%3};"
        : "+f"(c[0]), "+f"(c[1]), "+f"(c[2]), "+f"(c[3])
        : "r"(a[0]), "r"(a[1]), "r"(a[2]), "r"(a[3]), "r"(b[0]), "r"(b[1]));
}
__device__ __forceinline__ void split_bf16(float v, __nv_bfloat16& h, __nv_bfloat16& l) {
    h = __float2bfloat16(v);
    l = __float2bfloat16(v - __bfloat162float(h));
}

// ------------------------- LayerNorm (fp32 out) -----------------------------
__global__ void ln_kernel(const float* __restrict__ x, const float* __restrict__ w,
                          const float* __restrict__ b, float* __restrict__ y, int rows)
{
    int warp = (blockIdx.x * blockDim.x + threadIdx.x) >> 5;
    int lane = threadIdx.x & 31;
    if (warp >= rows) return;
    const float* xr = x + (size_t)warp * CC;
    float vals[6];
    float sum = 0.f;
#pragma unroll
    for (int i = 0; i < 6; i++) {
        int idx = lane + 32 * i;
        vals[i] = (idx < CC) ? xr[idx] : 0.f;
        sum += vals[i];
    }
#pragma unroll
    for (int o = 16; o > 0; o >>= 1) sum += __shfl_xor_sync(0xffffffffu, sum, o);
    float mean = sum * (1.f / CC);
    float vs = 0.f;
#pragma unroll
    for (int i = 0; i < 6; i++) {
        int idx = lane + 32 * i;
        if (idx < CC) { float d = vals[i] - mean; vs += d * d; }
    }
#pragma unroll
    for (int o = 16; o > 0; o >>= 1) vs += __shfl_xor_sync(0xffffffffu, vs, o);
    float rstd = rsqrtf(vs * (1.f / CC) + 1e-5f);
    float* yr = y + (size_t)warp * CC;
#pragma unroll
    for (int i = 0; i < 6; i++) {
        int idx = lane + 32 * i;
        if (idx < CC) yr[idx] = (vals[i] - mean) * rstd * w[idx] + b[idx];
    }
}

// ------------------------- LayerNorm2 -> bf16 split padded [.,192] ----------
__global__ void ln2_split_kernel(const float* __restrict__ x, const float* __restrict__ w,
                                 const float* __restrict__ b,
                                 __nv_bfloat16* __restrict__ oh, __nv_bfloat16* __restrict__ ol,
                                 int rows)
{
    int warp = (blockIdx.x * blockDim.x + threadIdx.x) >> 5;
    int lane = threadIdx.x & 31;
    if (warp >= rows) return;
    const float* xr = x + (size_t)warp * CC;
    float vals[6];
    float sum = 0.f;
#pragma unroll
    for (int i = 0; i < 6; i++) {
        int idx = lane + 32 * i;
        vals[i] = (idx < CC) ? xr[idx] : 0.f;
        sum += vals[i];
    }
#pragma unroll
    for (int o = 16; o > 0; o >>= 1) sum += __shfl_xor_sync(0xffffffffu, sum, o);
    float mean = sum * (1.f / CC);
    float vs = 0.f;
#pragma unroll
    for (int i = 0; i < 6; i++) {
        int idx = lane + 32 * i;
        if (idx < CC) { float d = vals[i] - mean; vs += d * d; }
    }
#pragma unroll
    for (int o = 16; o > 0; o >>= 1) vs += __shfl_xor_sync(0xffffffffu, vs, o);
    float rstd = rsqrtf(vs * (1.f / CC) + 1e-5f);
    __nv_bfloat16* hr = oh + (size_t)warp * KP_180;
    __nv_bfloat16* lr = ol + (size_t)warp * KP_180;
#pragma unroll
    for (int i = 0; i < 6; i++) {
        int idx = lane + 32 * i;
        float v = (idx < CC) ? (vals[i] - mean) * rstd * w[idx] + b[idx] : 0.f;
        __nv_bfloat16 h, l; split_bf16(v, h, l);
        hr[idx] = h; lr[idx] = l;
    }
}

// ------------------------- DWT2 -> bf16 split padded [HPIX,768] -------------
__global__ void dwt_split_kernel(__nv_bfloat16* __restrict__ oh, __nv_bfloat16* __restrict__ ol)
{
    int idx = blockIdx.x * blockDim.x + threadIdx.x;
    if (idx >= HPIX * KP_XD) return;
    int c4  = idx % KP_XD;
    int pix = idx / KP_XD;
    float v = 0.f;
    if (c4 < C4) {
        int x2  = pix % 128;
        int y2  = (pix / 128) % 128;
        int bi  = pix / (128 * 128);
        int band = c4 / CC;
        int c    = c4 % CC;
        size_t base = (((size_t)bi * 256 + 2 * y2) * 256 + 2 * x2) * CC + c;
        float a  = g_xn[base];
        float bq = g_xn[base + CC];
        float cq = g_xn[base + 256 * CC];
        float dq = g_xn[base + 256 * CC + CC];
        if      (band == 0) v = ( a + bq + cq + dq);
        else if (band == 1) v = (-a - bq + cq + dq);
        else if (band == 2) v = (-a + bq - cq + dq);
        else                v = ( a - bq - cq + dq);
        v *= 0.5f;
    }
    __nv_bfloat16 h, l; split_bf16(v, h, l);
    oh[idx] = h; ol[idx] = l;
}

// ------------------------- IDWT2 -> bf16 split padded [NPIX,192] ------------
__global__ void idwt_split_kernel(__nv_bfloat16* __restrict__ oh, __nv_bfloat16* __restrict__ ol)
{
    int idx = blockIdx.x * blockDim.x + threadIdx.x;
    if (idx >= NPIX * KP_180) return;
    int c   = idx % KP_180;
    int pix = idx / KP_180;
    float v = 0.f;
    if (c < CC) {
        int x   = pix % 256;
        int y   = (pix / 256) % 256;
        int bi  = pix / (256 * 256);
        int hy = y >> 1, hx = x >> 1;
        int win = bi * 256 + (hy >> 3) * 16 + (hx >> 3);
        int qq  = (hy & 7) * 8 + (hx & 7);
        const float* p = g_o + ((size_t)win * NQ + qq) * C4 + c;
        float ll = p[0], lh = p[CC], hl = p[2 * CC], hh = p[3 * CC];
        int py = y & 1, px = x & 1;
        if      (py == 0 && px == 0) v = (ll - lh - hl + hh);
        else if (py == 0 && px == 1) v = (ll - lh + hl - hh);
        else if (py == 1 && px == 0) v = (ll + lh - hl - hh);
        else                         v = (ll + lh + hl + hh);
        v *= 0.5f;
    }
    __nv_bfloat16 h, l; split_bf16(v, h, l);
    oh[idx] = h; ol[idx] = l;
}

// ------------------------- weight transpose + split + pad -------------------
// W [K,N] fp32 -> Wt hi/lo [rows, Kp] bf16
__global__ void wt_split_kernel(const float* __restrict__ W,
                                __nv_bfloat16* __restrict__ wh, __nv_bfloat16* __restrict__ wl,
                                int K, int N, int Kp, int rows)
{
    int idx = blockIdx.x * blockDim.x + threadIdx.x;
    if (idx >= rows * Kp) return;
    int n = idx / Kp, k = idx % Kp;
    float v = (n < N && k < K) ? W[(size_t)k * N + n] : 0.f;
    __nv_bfloat16 h, l; split_bf16(v, h, l);
    wh[idx] = h; wl[idx] = l;
}

// ------------------------- mma.sync split-bf16 GEMM -------------------------
// C[128x128 tile] = (Ah+Al)[M,Kp] @ (Wh+Wl)^T[rows,Kp]  (3-term split)
// epilogue: +bias, optional exact GELU, optional residual; out fp32 [M,N] or
// bf16-split padded [M,ldo].
#define LDA 72               // smem row stride (bf16 elements), 144B
#define SM_TILE (128 * LDA)  // per-operand tile elems
#define SM_GEMM (4 * SM_TILE * 2)

__global__ void __launch_bounds__(256)
hgemm_kernel(const __nv_bfloat16* __restrict__ Ah, const __nv_bfloat16* __restrict__ Al,
             const __nv_bfloat16* __restrict__ Wh, const __nv_bfloat16* __restrict__ Wl,
             const float* __restrict__ bias, const float* __restrict__ res,
             float* __restrict__ Cf, __nv_bfloat16* __restrict__ Oh, __nv_bfloat16* __restrict__ Ol,
             int Kp, int N, int ldo, int gelu)
{
    extern __shared__ __nv_bfloat16 sm[];
    __nv_bfloat16* sAh = sm;
    __nv_bfloat16* sAl = sAh + SM_TILE;
    __nv_bfloat16* sBh = sAl + SM_TILE;
    __nv_bfloat16* sBl = sBh + SM_TILE;

    int tid = threadIdx.x, wid = tid >> 5, lane = tid & 31;
    int m0 = blockIdx.y * 128, n0 = blockIdx.x * 128;
    int wm = (wid >> 2) * 64, wn = (wid & 3) * 32;

    float acc[4][4][4];
#pragma unroll
    for (int i = 0; i < 4; i++)
#pragma unroll
        for (int j = 0; j < 4; j++)
#pragma unroll
            for (int t = 0; t < 4; t++) acc[i][j][t] = 0.f;

    int kw = Kp >> 3;  // uint4 per row
    const uint4* Ah4 = (const uint4*)Ah + (size_t)m0 * kw;
    const uint4* Al4 = (const uint4*)Al + (size_t)m0 * kw;
    const uint4* Wh4 = (const uint4*)Wh + (size_t)n0 * kw;
    const uint4* Wl4 = (const uint4*)Wl + (size_t)n0 * kw;

    // ldmatrix base addresses (per-lane)
    int a_r = lane & 15, a_c8 = lane >> 4;          // A: row, k-half
    int b_r = lane & 7,  b_c8 = (lane >> 3) & 1;    // B: row, k-half (lanes 0-15 used)

    int chunks = Kp >> 6;
    for (int ch = 0; ch < chunks; ch++) {
        int kc = ch << 3;
#pragma unroll
        for (int i = tid; i < 1024; i += 256) {
            int r = i >> 3, c = i & 7;
            *(uint4*)(sAh + r * LDA + c * 8) = Ah4[(size_t)r * kw + kc + c];
            *(uint4*)(sAl + r * LDA + c * 8) = Al4[(size_t)r * kw + kc + c];
            *(uint4*)(sBh + r * LDA + c * 8) = Wh4[(size_t)r * kw + kc + c];
            *(uint4*)(sBl + r * LDA + c * 8) = Wl4[(size_t)r * kw + kc + c];
        }
        __syncthreads();
#pragma unroll
        for (int ks = 0; ks < 4; ks++) {
            int kk = ks * 16;
            uint32_t bh[4][2], bl[4][2];
#pragma unroll
            for (int ni = 0; ni < 4; ni++) {
                uint32_t addr_h = smem_u32(sBh + (wn + ni * 8 + b_r) * LDA + kk + b_c8 * 8);
                uint32_t addr_l = smem_u32(sBl + (wn + ni * 8 + b_r) * LDA + kk + b_c8 * 8);
                ldm_x2(bh[ni][0], bh[ni][1], addr_h);
                ldm_x2(bl[ni][0], bl[ni][1], addr_l);
            }
#pragma unroll
            for (int mi = 0; mi < 4; mi++) {
                uint32_t ah[4], al_[4];
                uint32_t addr_h = smem_u32(sAh + (wm + mi * 16 + a_r) * LDA + kk + a_c8 * 8);
                uint32_t addr_l = smem_u32(sAl + (wm + mi * 16 + a_r) * LDA + kk + a_c8 * 8);
                ldm_x4(ah[0], ah[1], ah[2], ah[3], addr_h);
                ldm_x4(al_[0], al_[1], al_[2], al_[3], addr_l);
#pragma unroll
                for (int ni = 0; ni < 4; ni++) {
                    mma_bf16(acc[mi][ni], ah,  bh[ni]);
                    mma_bf16(acc[mi][ni], ah,  bl[ni]);
                    mma_bf16(acc[mi][ni], al_, bh[ni]);
                }
            }
        }
        __syncthreads();
    }

    // epilogue
    int er = lane >> 2, ec = (lane & 3) * 2;
#pragma unroll
    for (int mi = 0; mi < 4; mi++) {
#pragma unroll
        for (int ni = 0; ni < 4; ni++) {
            float* a = acc[mi][ni];
#pragma unroll
            for (int t = 0; t < 4; t++) {
                int row = m0 + wm + mi * 16 + er + (t >> 1) * 8;
                int col = n0 + wn + ni * 8 + ec + (t & 1);
                if (Oh == nullptr) {
                    if (col < N) {
                        float v = a[t] + bias[col];
                        if (gelu) v = 0.5f * v * (1.f + erff(v * 0.70710678118654752f));
                        if (res)  v += res[(size_t)row * N + col];
                        Cf[(size_t)row * N + col] = v;
                    }
                } else {
                    if (col < ldo) {
                        float v = 0.f;
                        if (col < N) {
                            v = a[t] + bias[col];
                            if (gelu) v = 0.5f * v * (1.f + erff(v * 0.70710678118654752f));
                        }
                        __nv_bfloat16 h, l; split_bf16(v, h, l);
                        Oh[(size_t)row * ldo + col] = h;
                        Ol[(size_t)row * ldo + col] = l;
                    }
                }
            }
        }
    }
}

// ------------------------- relative position bias gather --------------------
__global__ void bias_kernel(const int* __restrict__ rpi, const float* __restrict__ rpb)
{
    int idx = blockIdx.x * blockDim.x + threadIdx.x;
    if (idx >= NH_ * NQ * NKV) return;
    int h = idx / (NQ * NKV);
    int r = (idx / NKV) % NQ;
    int n = idx % NKV;
    g_bias[idx] = rpb[rpi[r * NKV + n] * NH_ + h];
}

// ------------------------- attention: one block per (window, head) ----------
#define SMEM_ATTN ((NQ * HD + NKV * HD + NQ * NKV) * 4)
__global__ void attn_kernel()
{
    extern __shared__ float smf[];
    float* qs = smf;
    float* ks = smf + NQ * HD;
    float* s  = smf + NQ * HD + NKV * HD;

    int win = blockIdx.x;
    int hh  = blockIdx.y;
    int tid = threadIdx.x;
    int bi = win / 256;
    int rem = win % 256;
    int wy = rem / 16, wx = rem % 16;
    const float scale = 0.18257418583505536f;

    for (int i = tid; i < NQ * HD; i += 256) {
        int qq = i / HD, d = i % HD;
        int y = wy * 8 + (qq >> 3), x = wx * 8 + (qq & 7);
        size_t pix = ((size_t)bi * 128 + y) * 128 + x;
        qs[i] = g_q[pix * CC + hh * HD + d] * scale;
    }
    for (int i = tid; i < NKV * HD; i += 256) {
        int n = i / HD, d = i % HD;
        int y = wy * 8 + n / 12 - 4, x = wx * 8 + n % 12 - 4;
        float v = 0.f;
        if (y >= 0 && y < 128 && x >= 0 && x < 128) {
            size_t pix = ((size_t)bi * 128 + y) * 128 + x;
            v = g_k[pix * CC + hh * HD + d];
        }
        ks[i] = v;
    }
    __syncthreads();

    for (int i = tid; i < NQ * NKV; i += 256) {
        int qq = i / NKV, n = i % NKV;
        float acc = g_bias[(hh * NQ + qq) * NKV + n];
        const float* qp = qs + qq * HD;
        const float* kp = ks + n * HD;
#pragma unroll
        for (int d = 0; d < HD; d++) acc += qp[d] * kp[d];
        s[i] = acc;
    }
    __syncthreads();

    {
        int warp = tid >> 5, lane = tid & 31;
        for (int r = warp * 8; r < warp * 8 + 8; r++) {
            float* row = s + r * NKV;
            float m = -1e30f;
            for (int n = lane; n < NKV; n += 32) m = fmaxf(m, row[n]);
#pragma unroll
            for (int o = 16; o > 0; o >>= 1) m = fmaxf(m, __shfl_xor_sync(0xffffffffu, m, o));
            float sum = 0.f;
            for (int n = lane; n < NKV; n += 32) {
                float e = __expf(row[n] - m);
                row[n] = e;
                sum += e;
            }
#pragma unroll
            for (int o = 16; o > 0; o >>= 1) sum += __shfl_xor_sync(0xffffffffu, sum, o);
            float inv = 1.f / sum;
            for (int n = lane; n < NKV; n += 32) row[n] *= inv;
        }
    }
    __syncthreads();

    for (int c0 = 0; c0 < HD4; c0 += HD) {
        for (int i = tid; i < NKV * HD; i += 256) {
            int n = i / HD, d = i % HD;
            int y = wy * 8 + n / 12 - 4, x = wx * 8 + n % 12 - 4;
            float v = 0.f;
            if (y >= 0 && y < 128 && x >= 0 && x < 128) {
                size_t pix = ((size_t)bi * 128 + y) * 128 + x;
                v = g_v[pix * C4 + hh * HD4 + c0 + d];
            }
            ks[i] = v;
        }
        __syncthreads();
        for (int i = tid; i < NQ * HD; i += 256) {
            int qq = i / HD, d = i % HD;
            const float* sp = s + qq * NKV;
            float acc = 0.f;
#pragma unroll 4
            for (int n = 0; n < NKV; n++) acc += sp[n] * ks[n * HD + d];
            g_o[((size_t)win * NQ + qq) * C4 + hh * HD4 + c0 + d] = acc;
        }
        __syncthreads();
    }
}

// ------------------------- launcher -----------------------------------------
extern "C" void kernel_launch(void* const* d_in, const int* in_sizes, int n_in,
                              void* d_out, int out_size)
{
    const float* x       = (const float*)d_in[0];
    const int*   rpi     = (const int*)  d_in[2];
    const float* norm1_w = (const float*)d_in[5];
    const float* norm1_b = (const float*)d_in[6];
    const float* q_w     = (const float*)d_in[9];
    const float* q_b     = (const float*)d_in[10];
    const float* k_w     = (const float*)d_in[11];
    const float* k_b     = (const float*)d_in[12];
    const float* v_w     = (const float*)d_in[13];
    const float* v_b     = (const float*)d_in[14];
    const float* rpb     = (const float*)d_in[15];
    const float* proj_w  = (const float*)d_in[16];
    const float* proj_b  = (const float*)d_in[17];
    const float* norm2_w = (const float*)d_in[18];
    const float* norm2_b = (const float*)d_in[19];
    const float* fc1_w   = (const float*)d_in[20];
    const float* fc1_b   = (const float*)d_in[21];
    const float* fc2_w   = (const float*)d_in[22];
    const float* fc2_b   = (const float*)d_in[23];
    float* out = (float*)d_out;

    void *p_xn, *p_q, *p_k, *p_v, *p_ah, *p_al, *p_wh, *p_wl;
    cudaGetSymbolAddress(&p_xn, g_xn);
    cudaGetSymbolAddress(&p_q,  g_q);
    cudaGetSymbolAddress(&p_k,  g_k);
    cudaGetSymbolAddress(&p_v,  g_v);
    cudaGetSymbolAddress(&p_ah, g_ah);
    cudaGetSymbolAddress(&p_al, g_al);
    cudaGetSymbolAddress(&p_wh, g_wh);
    cudaGetSymbolAddress(&p_wl, g_wl);
    float* xn = (float*)p_xn;
    float* qf = (float*)p_q;
    float* kf = (float*)p_k;
    float* vf = (float*)p_v;
    __nv_bfloat16* ah = (__nv_bfloat16*)p_ah;
    __nv_bfloat16* al = (__nv_bfloat16*)p_al;
    __nv_bfloat16* wh = (__nv_bfloat16*)p_wh;
    __nv_bfloat16* wl = (__nv_bfloat16*)p_wl;

    cudaFuncSetAttribute(attn_kernel, cudaFuncAttributeMaxDynamicSharedMemorySize, SMEM_ATTN);
    cudaFuncSetAttribute(hgemm_kernel, cudaFuncAttributeMaxDynamicSharedMemorySize, SM_GEMM);

    // 0. weight conversions (transpose + split + pad)
    {
        int n;
        n = 256 * 768; wt_split_kernel<<<(n + 255) / 256, 256>>>(q_w,    wh + WOFF_Q,    wl + WOFF_Q,    720, 180, 768, 256);
        n = 256 * 768; wt_split_kernel<<<(n + 255) / 256, 256>>>(k_w,    wh + WOFF_K,    wl + WOFF_K,    720, 180, 768, 256);
        n = 768 * 768; wt_split_kernel<<<(n + 255) / 256, 256>>>(v_w,    wh + WOFF_V,    wl + WOFF_V,    720, 720, 768, 768);
        n = 256 * 192; wt_split_kernel<<<(n + 255) / 256, 256>>>(proj_w, wh + WOFF_PROJ, wl + WOFF_PROJ, 180, 180, 192, 256);
        n = 512 * 192; wt_split_kernel<<<(n + 255) / 256, 256>>>(fc1_w,  wh + WOFF_FC1,  wl + WOFF_FC1,  180, 360, 192, 512);
        n = 256 * 384; wt_split_kernel<<<(n + 255) / 256, 256>>>(fc2_w,  wh + WOFF_FC2,  wl + WOFF_FC2,  360, 180, 384, 256);
    }
    // 1. LN1 (fp32)
    ln_kernel<<<NPIX / 8, 256>>>(x, norm1_w, norm1_b, xn, NPIX);
    // 2. DWT -> bf16 split (slot A)
    dwt_split_kernel<<<(HPIX * KP_XD + 255) / 256, 256>>>(ah, al);
    // 3-5. Q,K,V projections (tensor cores via mma.sync)
    {
        dim3 g2(2, HPIX / 128);
        hgemm_kernel<<<g2, 256, SM_GEMM>>>(ah, al, wh + WOFF_Q, wl + WOFF_Q, q_b, nullptr, qf, nullptr, nullptr, 768, 180, 0, 0);
        hgemm_kernel<<<g2, 256, SM_GEMM>>>(ah, al, wh + WOFF_K, wl + WOFF_K, k_b, nullptr, kf, nullptr, nullptr, 768, 180, 0, 0);
        dim3 g6(6, HPIX / 128);
        hgemm_kernel<<<g6, 256, SM_GEMM>>>(ah, al, wh + WOFF_V, wl + WOFF_V, v_b, nullptr, vf, nullptr, nullptr, 768, 720, 0, 0);
    }
    // 6. rel-pos bias table
    bias_kernel<<<(NH_ * NQ * NKV + 255) / 256, 256>>>(rpi, rpb);
    // 7. attention
    {
        dim3 g(NWIN, NH_);
        attn_kernel<<<g, 256, SMEM_ATTN>>>();
    }
    // 8. IDWT -> bf16 split (slot A)
    idwt_split_kernel<<<(NPIX * KP_180 + 255) / 256, 256>>>(ah, al);
    // 9. proj + residual -> out (x1)
    {
        dim3 g(2, NPIX / 128);
        hgemm_kernel<<<g, 256, SM_GEMM>>>(ah, al, wh + WOFF_PROJ, wl + WOFF_PROJ, proj_b, x, out, nullptr, nullptr, 192, 180, 0, 0);
    }
    // 10. LN2 -> bf16 split (slot A)
    ln2_split_kernel<<<NPIX / 8, 256>>>(out, norm2_w, norm2_b, ah, al, NPIX);
    // 11. fc1 + GELU -> bf16 split (slot B)
    {
        dim3 g(3, NPIX / 128);
        hgemm_kernel<<<g, 256, SM_GEMM>>>(ah, al, wh + WOFF_FC1, wl + WOFF_FC1, fc1_b, nullptr, nullptr, ah + SLOTB, al + SLOTB, 192, 360, 384, 1);
    }
    // 12. fc2 + residual(x1) -> out
    {
        dim3 g(2, NPIX / 128);
        hgemm_kernel<<<g, 256, SM_GEMM>>>(ah + SLOTB, al + SLOTB, wh + WOFF_FC2, wl + WOFF_FC2, fc2_b, out, out, nullptr, nullptr, 384, 180, 0, 0);
    }
}

// round 10
// speedup vs baseline: 2.6865x; 1.1742x over previous
#include <cuda_runtime.h>
#include <cuda_bf16.h>
#include <math.h>
#include <stdint.h>

// Problem constants
#define BB    2
#define HH    256
#define WWd   256
#define CC    180
#define NH_   6
#define HD    30      // CC/NH
#define C4    720     // 4*CC
#define HD4   120     // 4*HD
#define NPIX  131072  // BB*HH*WWd
#define HPIX  32768   // BB*128*128
#define NWIN  512     // BB*16*16
#define NQ    64
#define NKV   144

// Padded dims
#define KP_XD   768   // 720 -> 768
#define KP_180  192   // 180 -> 192
#define KP_360  384   // 360 -> 384

#define SLOTB   25165824   // 32768*768 == 131072*192

// ------------------------- scratch (device globals) -------------------------
__device__ float g_xn[23592960];           // LN1 out (B,256,256,180)
__device__ float g_q [5898240];            // (B,128,128,180)
__device__ float g_k [5898240];            // (B,128,128,180)
__device__ float g_v [23592960];           // (B,128,128,720)
__device__ float g_o [23592960];           // (512,64,720)
__device__ float g_bias[55296];            // (6,64,144)
__device__ float g_bqkv[1280];             // packed qkv bias
__device__ __nv_bfloat16 g_ah[75497472];   // activations hi (slotA + slotB)
__device__ __nv_bfloat16 g_al[75497472];   // activations lo
__device__ __nv_bfloat16 g_wh[1228800];    // weights hi (transposed, padded)
__device__ __nv_bfloat16 g_wl[1228800];    // weights lo

// weight pool offsets (rows x Kp); Q|K|V contiguous -> fused qkv GEMM
#define WOFF_Q    0         // 256 x 768
#define WOFF_K    196608    // 256 x 768
#define WOFF_V    393216    // 768 x 768
#define WOFF_PROJ 983040    // 256 x 192
#define WOFF_FC1  1032192   // 512 x 192
#define WOFF_FC2  1130496   // 256 x 384

// ------------------------- helpers ------------------------------------------
__device__ __forceinline__ uint32_t smem_u32(const void* p) {
    uint32_t a;
    asm("{ .reg .u64 t; cvta.to.shared.u64 t, %1; cvt.u32.u64 %0, t; }" : "=r"(a) : "l"(p));
    return a;
}
__device__ __forceinline__ void cpa16(uint32_t s, const void* g) {
    asm volatile("cp.async.cg.shared.global [%0], [%1], 16;" :: "r"(s), "l"(g));
}
__device__ __forceinline__ void ldm_x4(uint32_t& r0, uint32_t& r1, uint32_t& r2, uint32_t& r3,
                                       uint32_t addr) {
    asm volatile("ldmatrix.sync.aligned.m8n8.x4.shared.b16 {%0,%1,%2,%3}, [%4];"
        : "=r"(r0), "=r"(r1), "=r"(r2), "=r"(r3) : "r"(addr));
}
__device__ __forceinline__ void ldm_x2(uint32_t& r0, uint32_t& r1, uint32_t addr) {
    asm volatile("ldmatrix.sync.aligned.m8n8.x2.shared.b16 {%0,%1}, [%2];"
        : "=r"(r0), "=r"(r1) : "r"(addr));
}
__device__ __forceinline__ void mma_bf16(float* c, const uint32_t* a, const uint32_t* b) {
    asm volatile("mma.sync.aligned.m16n8k16.row.col.f32.bf16.bf16.f32 "
        "{%0,%1,%2,%3}, {%4,%5,%6,%7}, {%8,%9}, {%0,%1,%2,%3};"
        : "+f"(c[0]), "+f"(c[1]), "+f"(c[2]), "+f"(c[3])
        : "r"(a[0]), "r"(a[1]), "r"(a[2]), "r"(a[3]), "r"(b[0]), "r"(b[1]));
}
__device__ __forceinline__ void split_bf16(float v, __nv_bfloat16& h, __nv_bfloat16& l) {
    h = __float2bfloat16(v);
    l = __float2bfloat16(v - __bfloat162float(h));
}

// ------------------------- LayerNorm (fp32 out) -----------------------------
__global__ void ln_kernel(const float* __restrict__ x, const float* __restrict__ w,
                          const float* __restrict__ b, float* __restrict__ y, int rows)
{
    int warp = (blockIdx.x * blockDim.x + threadIdx.x) >> 5;
    int lane = threadIdx.x & 31;
    if (warp >= rows) return;
    const float* xr = x + (size_t)warp * CC;
    float vals[6];
    float sum = 0.f;
#pragma unroll
    for (int i = 0; i < 6; i++) {
        int idx = lane + 32 * i;
        vals[i] = (idx < CC) ? xr[idx] : 0.f;
        sum += vals[i];
    }
#pragma unroll
    for (int o = 16; o > 0; o >>= 1) sum += __shfl_xor_sync(0xffffffffu, sum, o);
    float mean = sum * (1.f / CC);
    float vs = 0.f;
#pragma unroll
    for (int i = 0; i < 6; i++) {
        int idx = lane + 32 * i;
        if (idx < CC) { float d = vals[i] - mean; vs += d * d; }
    }
#pragma unroll
    for (int o = 16; o > 0; o >>= 1) vs += __shfl_xor_sync(0xffffffffu, vs, o);
    float rstd = rsqrtf(vs * (1.f / CC) + 1e-5f);
    float* yr = y + (size_t)warp * CC;
#pragma unroll
    for (int i = 0; i < 6; i++) {
        int idx = lane + 32 * i;
        if (idx < CC) yr[idx] = (vals[i] - mean) * rstd * w[idx] + b[idx];
    }
}

// ------------------------- LayerNorm2 -> bf16 split padded [.,192] ----------
__global__ void ln2_split_kernel(const float* __restrict__ x, const float* __restrict__ w,
                                 const float* __restrict__ b,
                                 __nv_bfloat16* __restrict__ oh, __nv_bfloat16* __restrict__ ol,
                                 int rows)
{
    int warp = (blockIdx.x * blockDim.x + threadIdx.x) >> 5;
    int lane = threadIdx.x & 31;
    if (warp >= rows) return;
    const float* xr = x + (size_t)warp * CC;
    float vals[6];
    float sum = 0.f;
#pragma unroll
    for (int i = 0; i < 6; i++) {
        int idx = lane + 32 * i;
        vals[i] = (idx < CC) ? xr[idx] : 0.f;
        sum += vals[i];
    }
#pragma unroll
    for (int o = 16; o > 0; o >>= 1) sum += __shfl_xor_sync(0xffffffffu, sum, o);
    float mean = sum * (1.f / CC);
    float vs = 0.f;
#pragma unroll
    for (int i = 0; i < 6; i++) {
        int idx = lane + 32 * i;
        if (idx < CC) { float d = vals[i] - mean; vs += d * d; }
    }
#pragma unroll
    for (int o = 16; o > 0; o >>= 1) vs += __shfl_xor_sync(0xffffffffu, vs, o);
    float rstd = rsqrtf(vs * (1.f / CC) + 1e-5f);
    __nv_bfloat16* hr = oh + (size_t)warp * KP_180;
    __nv_bfloat16* lr = ol + (size_t)warp * KP_180;
#pragma unroll
    for (int i = 0; i < 6; i++) {
        int idx = lane + 32 * i;
        float v = (idx < CC) ? (vals[i] - mean) * rstd * w[idx] + b[idx] : 0.f;
        __nv_bfloat16 h, l; split_bf16(v, h, l);
        hr[idx] = h; lr[idx] = l;
    }
}

// ------------------------- DWT2 -> bf16 split padded [HPIX,768] -------------
__global__ void dwt_split_kernel(__nv_bfloat16* __restrict__ oh, __nv_bfloat16* __restrict__ ol)
{
    int idx = blockIdx.x * blockDim.x + threadIdx.x;
    if (idx >= HPIX * KP_XD) return;
    int c4  = idx % KP_XD;
    int pix = idx / KP_XD;
    float v = 0.f;
    if (c4 < C4) {
        int x2  = pix % 128;
        int y2  = (pix / 128) % 128;
        int bi  = pix / (128 * 128);
        int band = c4 / CC;
        int c    = c4 % CC;
        size_t base = (((size_t)bi * 256 + 2 * y2) * 256 + 2 * x2) * CC + c;
        float a  = g_xn[base];
        float bq = g_xn[base + CC];
        float cq = g_xn[base + 256 * CC];
        float dq = g_xn[base + 256 * CC + CC];
        if      (band == 0) v = ( a + bq + cq + dq);
        else if (band == 1) v = (-a - bq + cq + dq);
        else if (band == 2) v = (-a + bq - cq + dq);
        else                v = ( a - bq - cq + dq);
        v *= 0.5f;
    }
    __nv_bfloat16 h, l; split_bf16(v, h, l);
    oh[idx] = h; ol[idx] = l;
}

// ------------------------- IDWT2 -> bf16 split padded [NPIX,192] ------------
__global__ void idwt_split_kernel(__nv_bfloat16* __restrict__ oh, __nv_bfloat16* __restrict__ ol)
{
    int idx = blockIdx.x * blockDim.x + threadIdx.x;
    if (idx >= NPIX * KP_180) return;
    int c   = idx % KP_180;
    int pix = idx / KP_180;
    float v = 0.f;
    if (c < CC) {
        int x   = pix % 256;
        int y   = (pix / 256) % 256;
        int bi  = pix / (256 * 256);
        int hy = y >> 1, hx = x >> 1;
        int win = bi * 256 + (hy >> 3) * 16 + (hx >> 3);
        int qq  = (hy & 7) * 8 + (hx & 7);
        const float* p = g_o + ((size_t)win * NQ + qq) * C4 + c;
        float ll = p[0], lh = p[CC], hl = p[2 * CC], hh = p[3 * CC];
        int py = y & 1, px = x & 1;
        if      (py == 0 && px == 0) v = (ll - lh - hl + hh);
        else if (py == 0 && px == 1) v = (ll - lh + hl - hh);
        else if (py == 1 && px == 0) v = (ll + lh - hl - hh);
        else                         v = (ll + lh + hl + hh);
        v *= 0.5f;
    }
    __nv_bfloat16 h, l; split_bf16(v, h, l);
    oh[idx] = h; ol[idx] = l;
}

// ------------------------- weight transpose + split + pad -------------------
__global__ void wt_split_kernel(const float* __restrict__ W,
                                __nv_bfloat16* __restrict__ wh, __nv_bfloat16* __restrict__ wl,
                                int K, int N, int Kp, int rows)
{
    int idx = blockIdx.x * blockDim.x + threadIdx.x;
    if (idx >= rows * Kp) return;
    int n = idx / Kp, k = idx % Kp;
    float v = (n < N && k < K) ? W[(size_t)k * N + n] : 0.f;
    __nv_bfloat16 h, l; split_bf16(v, h, l);
    wh[idx] = h; wl[idx] = l;
}

// ------------------------- packed qkv bias (race-free) -----------------------
__global__ void biasqkv_kernel(const float* __restrict__ qb, const float* __restrict__ kb,
                               const float* __restrict__ vb)
{
    int i = blockIdx.x * blockDim.x + threadIdx.x;
    if (i >= 1280) return;
    float v = 0.f;
    if (i < 256)       { if (i < 180) v = qb[i]; }
    else if (i < 512)  { int c = i - 256; if (c < 180) v = kb[c]; }
    else               { int c = i - 512; if (c < 720) v = vb[c]; }
    g_bqkv[i] = v;
}

// ------------------------- pipelined mma.sync split-bf16 GEMM ----------------
// C[128x128 tile] = (Ah+Al)[M,Kp] @ (Wh+Wl)^T[rows,Kp]  (3-term split)
// mode 0: fp32 out (+bias, optional residual)
// mode 1: GELU + bf16-split out [M,ldo]
// mode 2: qkv routing (cols 0-255 -> q, 256-511 -> k, 512-1279 -> v)
#define LDA 72                     // smem row stride (bf16), 144B
#define TILE_B (128 * LDA * 2)     // bytes per operand tile = 18432
#define STAGE_B (4 * TILE_B)       // 73728
#define SM_GEMM (2 * STAGE_B)      // 147456

__global__ void __launch_bounds__(256)
hgemm_kernel(const __nv_bfloat16* __restrict__ Ah, const __nv_bfloat16* __restrict__ Al,
             const __nv_bfloat16* __restrict__ Wh, const __nv_bfloat16* __restrict__ Wl,
             const float* __restrict__ bias, const float* __restrict__ res,
             float* __restrict__ Cf, float* __restrict__ aux1, float* __restrict__ aux2,
             int Kp, int N, int ldo, int mode)
{
    extern __shared__ char smc[];
    uint32_t ub = smem_u32(smc);

    int tid = threadIdx.x, wid = tid >> 5, lane = tid & 31;
    int m0 = blockIdx.y * 128, n0 = blockIdx.x * 128;
    int wm = (wid >> 2) * 64, wn = (wid & 3) * 32;

    float acc[4][4][4];
#pragma unroll
    for (int i = 0; i < 4; i++)
#pragma unroll
        for (int j = 0; j < 4; j++)
#pragma unroll
            for (int t = 0; t < 4; t++) acc[i][j][t] = 0.f;

    int kw = Kp >> 3;  // uint4 per row
    const uint4* Ah4 = (const uint4*)Ah + (size_t)m0 * kw;
    const uint4* Al4 = (const uint4*)Al + (size_t)m0 * kw;
    const uint4* Wh4 = (const uint4*)Wh + (size_t)n0 * kw;
    const uint4* Wl4 = (const uint4*)Wl + (size_t)n0 * kw;

    int a_r = lane & 15, a_c8 = lane >> 4;
    int b_r = lane & 7,  b_c8 = (lane >> 3) & 1;

    int chunks = Kp >> 6;

#define LOAD_CHUNK(CH, ST)                                                     \
    {                                                                          \
        uint32_t base = ub + (ST) * STAGE_B;                                   \
        int kc = (CH) << 3;                                                    \
        _Pragma("unroll")                                                      \
        for (int i = tid; i < 1024; i += 256) {                                \
            int r = i >> 3, c = i & 7;                                         \
            uint32_t o = (uint32_t)(r * LDA + c * 8) * 2;                      \
            size_t go = (size_t)r * kw + kc + c;                               \
            cpa16(base + o,              Ah4 + go);                            \
            cpa16(base + TILE_B + o,     Al4 + go);                            \
            cpa16(base + 2 * TILE_B + o, Wh4 + go);                            \
            cpa16(base + 3 * TILE_B + o, Wl4 + go);                            \
        }                                                                      \
        asm volatile("cp.async.commit_group;" ::: "memory");                   \
    }

    LOAD_CHUNK(0, 0);
    for (int ch = 0; ch < chunks; ch++) {
        int st = ch & 1;
        if (ch + 1 < chunks) {
            LOAD_CHUNK(ch + 1, st ^ 1);
            asm volatile("cp.async.wait_group 1;" ::: "memory");
        } else {
            asm volatile("cp.async.wait_group 0;" ::: "memory");
        }
        __syncthreads();
        uint32_t base = ub + st * STAGE_B;
#pragma unroll
        for (int ks = 0; ks < 4; ks++) {
            int kk = ks * 16;
            uint32_t bh[4][2], bl[4][2];
#pragma unroll
            for (int ni = 0; ni < 4; ni++) {
                uint32_t ro = (uint32_t)((wn + ni * 8 + b_r) * LDA + kk + b_c8 * 8) * 2;
                ldm_x2(bh[ni][0], bh[ni][1], base + 2 * TILE_B + ro);
                ldm_x2(bl[ni][0], bl[ni][1], base + 3 * TILE_B + ro);
            }
#pragma unroll
            for (int mi = 0; mi < 4; mi++) {
                uint32_t ah[4], al_[4];
                uint32_t ro = (uint32_t)((wm + mi * 16 + a_r) * LDA + kk + a_c8 * 8) * 2;
                ldm_x4(ah[0], ah[1], ah[2], ah[3], base + ro);
                ldm_x4(al_[0], al_[1], al_[2], al_[3], base + TILE_B + ro);
#pragma unroll
                for (int ni = 0; ni < 4; ni++) {
                    mma_bf16(acc[mi][ni], ah,  bh[ni]);
                    mma_bf16(acc[mi][ni], ah,  bl[ni]);
                    mma_bf16(acc[mi][ni], al_, bh[ni]);
                }
            }
        }
        __syncthreads();
    }
#undef LOAD_CHUNK

    // epilogue
    int er = lane >> 2, ec = (lane & 3) * 2;
#pragma unroll
    for (int mi = 0; mi < 4; mi++) {
#pragma unroll
        for (int ni = 0; ni < 4; ni++) {
            float* a = acc[mi][ni];
#pragma unroll
            for (int t = 0; t < 4; t++) {
                int row = m0 + wm + mi * 16 + er + (t >> 1) * 8;
                int col = n0 + wn + ni * 8 + ec + (t & 1);
                if (mode == 0) {
                    if (col < N) {
                        float v = a[t] + bias[col];
                        if (res) v += res[(size_t)row * N + col];
                        Cf[(size_t)row * N + col] = v;
                    }
                } else if (mode == 1) {
                    if (col < ldo) {
                        float v = 0.f;
                        if (col < N) {
                            v = a[t] + bias[col];
                            v = 0.5f * v * (1.f + erff(v * 0.70710678118654752f));
                        }
                        __nv_bfloat16 h, l; split_bf16(v, h, l);
                        ((__nv_bfloat16*)aux1)[(size_t)row * ldo + col] = h;
                        ((__nv_bfloat16*)aux2)[(size_t)row * ldo + col] = l;
                    }
                } else {  // mode 2: qkv routing
                    float v = a[t] + g_bqkv[col];
                    if (col < 512) {
                        int c = col & 255;
                        if (c < 180) {
                            float* dst = (col < 256) ? Cf : aux1;
                            dst[(size_t)row * 180 + c] = v;
                        }
                    } else {
                        int c = col - 512;
                        if (c < 720)  // guard V padding columns (FIX: was unguarded -> OOB)
                            aux2[(size_t)row * 720 + c] = v;
                    }
                }
            }
        }
    }
}

// ------------------------- relative position bias gather --------------------
__global__ void bias_kernel(const int* __restrict__ rpi, const float* __restrict__ rpb)
{
    int idx = blockIdx.x * blockDim.x + threadIdx.x;
    if (idx >= NH_ * NQ * NKV) return;
    int h = idx / (NQ * NKV);
    int r = (idx / NKV) % NQ;
    int n = idx % NKV;
    g_bias[idx] = rpb[rpi[r * NKV + n] * NH_ + h];
}

// ------------------------- attention: one block per (window, head) ----------
#define SMEM_ATTN ((NQ * HD + NKV * HD + NQ * NKV) * 4)
__global__ void attn_kernel()
{
    extern __shared__ float smf[];
    float* qs = smf;
    float* ks = smf + NQ * HD;
    float* s  = smf + NQ * HD + NKV * HD;

    int win = blockIdx.x;
    int hh  = blockIdx.y;
    int tid = threadIdx.x;
    int bi = win / 256;
    int rem = win % 256;
    int wy = rem / 16, wx = rem % 16;
    const float scale = 0.18257418583505536f;

    for (int i = tid; i < NQ * HD; i += 256) {
        int qq = i / HD, d = i % HD;
        int y = wy * 8 + (qq >> 3), x = wx * 8 + (qq & 7);
        size_t pix = ((size_t)bi * 128 + y) * 128 + x;
        qs[i] = g_q[pix * CC + hh * HD + d] * scale;
    }
    for (int i = tid; i < NKV * HD; i += 256) {
        int n = i / HD, d = i % HD;
        int y = wy * 8 + n / 12 - 4, x = wx * 8 + n % 12 - 4;
        float v = 0.f;
        if (y >= 0 && y < 128 && x >= 0 && x < 128) {
            size_t pix = ((size_t)bi * 128 + y) * 128 + x;
            v = g_k[pix * CC + hh * HD + d];
        }
        ks[i] = v;
    }
    __syncthreads();

    for (int i = tid; i < NQ * NKV; i += 256) {
        int qq = i / NKV, n = i % NKV;
        float acc = g_bias[(hh * NQ + qq) * NKV + n];
        const float* qp = qs + qq * HD;
        const float* kp = ks + n * HD;
#pragma unroll
        for (int d = 0; d < HD; d++) acc += qp[d] * kp[d];
        s[i] = acc;
    }
    __syncthreads();

    {
        int warp = tid >> 5, lane = tid & 31;
        for (int r = warp * 8; r < warp * 8 + 8; r++) {
            float* row = s + r * NKV;
            float m = -1e30f;
            for (int n = lane; n < NKV; n += 32) m = fmaxf(m, row[n]);
#pragma unroll
            for (int o = 16; o > 0; o >>= 1) m = fmaxf(m, __shfl_xor_sync(0xffffffffu, m, o));
            float sum = 0.f;
            for (int n = lane; n < NKV; n += 32) {
                float e = __expf(row[n] - m);
                row[n] = e;
                sum += e;
            }
#pragma unroll
            for (int o = 16; o > 0; o >>= 1) sum += __shfl_xor_sync(0xffffffffu, sum, o);
            float inv = 1.f / sum;
            for (int n = lane; n < NKV; n += 32) row[n] *= inv;
        }
    }
    __syncthreads();

    for (int c0 = 0; c0 < HD4; c0 += HD) {
        for (int i = tid; i < NKV * HD; i += 256) {
            int n = i / HD, d = i % HD;
            int y = wy * 8 + n / 12 - 4, x = wx * 8 + n % 12 - 4;
            float v = 0.f;
            if (y >= 0 && y < 128 && x >= 0 && x < 128) {
                size_t pix = ((size_t)bi * 128 + y) * 128 + x;
                v = g_v[pix * C4 + hh * HD4 + c0 + d];
            }
            ks[i] = v;
        }
        __syncthreads();
        for (int i = tid; i < NQ * HD; i += 256) {
            int qq = i / HD, d = i % HD;
            const float* sp = s + qq * NKV;
            float acc = 0.f;
#pragma unroll 4
            for (int n = 0; n < NKV; n++) acc += sp[n] * ks[n * HD + d];
            g_o[((size_t)win * NQ + qq) * C4 + hh * HD4 + c0 + d] = acc;
        }
        __syncthreads();
    }
}

// ------------------------- launcher -----------------------------------------
extern "C" void kernel_launch(void* const* d_in, const int* in_sizes, int n_in,
                              void* d_out, int out_size)
{
    const float* x       = (const float*)d_in[0];
    const int*   rpi     = (const int*)  d_in[2];
    const float* norm1_w = (const float*)d_in[5];
    const float* norm1_b = (const float*)d_in[6];
    const float* q_w     = (const float*)d_in[9];
    const float* q_b     = (const float*)d_in[10];
    const float* k_w     = (const float*)d_in[11];
    const float* k_b     = (const float*)d_in[12];
    const float* v_w     = (const float*)d_in[13];
    const float* v_b     = (const float*)d_in[14];
    const float* rpb     = (const float*)d_in[15];
    const float* proj_w  = (const float*)d_in[16];
    const float* proj_b  = (const float*)d_in[17];
    const float* norm2_w = (const float*)d_in[18];
    const float* norm2_b = (const float*)d_in[19];
    const float* fc1_w   = (const float*)d_in[20];
    const float* fc1_b   = (const float*)d_in[21];
    const float* fc2_w   = (const float*)d_in[22];
    const float* fc2_b   = (const float*)d_in[23];
    float* out = (float*)d_out;

    void *p_xn, *p_q, *p_k, *p_v, *p_ah, *p_al, *p_wh, *p_wl;
    cudaGetSymbolAddress(&p_xn, g_xn);
    cudaGetSymbolAddress(&p_q,  g_q);
    cudaGetSymbolAddress(&p_k,  g_k);
    cudaGetSymbolAddress(&p_v,  g_v);
    cudaGetSymbolAddress(&p_ah, g_ah);
    cudaGetSymbolAddress(&p_al, g_al);
    cudaGetSymbolAddress(&p_wh, g_wh);
    cudaGetSymbolAddress(&p_wl, g_wl);
    float* xn = (float*)p_xn;
    float* qf = (float*)p_q;
    float* kf = (float*)p_k;
    float* vf = (float*)p_v;
    __nv_bfloat16* ah = (__nv_bfloat16*)p_ah;
    __nv_bfloat16* al = (__nv_bfloat16*)p_al;
    __nv_bfloat16* wh = (__nv_bfloat16*)p_wh;
    __nv_bfloat16* wl = (__nv_bfloat16*)p_wl;

    cudaFuncSetAttribute(attn_kernel, cudaFuncAttributeMaxDynamicSharedMemorySize, SMEM_ATTN);
    cudaFuncSetAttribute(hgemm_kernel, cudaFuncAttributeMaxDynamicSharedMemorySize, SM_GEMM);

    // 0. weight conversions + packed qkv bias
    {
        int n;
        n = 256 * 768; wt_split_kernel<<<(n + 255) / 256, 256>>>(q_w,    wh + WOFF_Q,    wl + WOFF_Q,    720, 180, 768, 256);
        n = 256 * 768; wt_split_kernel<<<(n + 255) / 256, 256>>>(k_w,    wh + WOFF_K,    wl + WOFF_K,    720, 180, 768, 256);
        n = 768 * 768; wt_split_kernel<<<(n + 255) / 256, 256>>>(v_w,    wh + WOFF_V,    wl + WOFF_V,    720, 720, 768, 768);
        n = 256 * 192; wt_split_kernel<<<(n + 255) / 256, 256>>>(proj_w, wh + WOFF_PROJ, wl + WOFF_PROJ, 180, 180, 192, 256);
        n = 512 * 192; wt_split_kernel<<<(n + 255) / 256, 256>>>(fc1_w,  wh + WOFF_FC1,  wl + WOFF_FC1,  180, 360, 192, 512);
        n = 256 * 384; wt_split_kernel<<<(n + 255) / 256, 256>>>(fc2_w,  wh + WOFF_FC2,  wl + WOFF_FC2,  360, 180, 384, 256);
        biasqkv_kernel<<<5, 256>>>(q_b, k_b, v_b);
    }
    // 1. LN1 (fp32)
    ln_kernel<<<NPIX / 8, 256>>>(x, norm1_w, norm1_b, xn, NPIX);
    // 2. DWT -> bf16 split (slot A)
    dwt_split_kernel<<<(HPIX * KP_XD + 255) / 256, 256>>>(ah, al);
    // 3. fused Q|K|V projection (pipelined tensor GEMM)
    {
        dim3 g(10, HPIX / 128);
        hgemm_kernel<<<g, 256, SM_GEMM>>>(ah, al, wh + WOFF_Q, wl + WOFF_Q, nullptr, nullptr,
                                          qf, kf, vf, 768, 1280, 0, 2);
    }
    // 4. rel-pos bias table
    bias_kernel<<<(NH_ * NQ * NKV + 255) / 256, 256>>>(rpi, rpb);
    // 5. attention
    {
        dim3 g(NWIN, NH_);
        attn_kernel<<<g, 256, SMEM_ATTN>>>();
    }
    // 6. IDWT -> bf16 split (slot A)
    idwt_split_kernel<<<(NPIX * KP_180 + 255) / 256, 256>>>(ah, al);
    // 7. proj + residual -> out (x1)
    {
        dim3 g(2, NPIX / 128);
        hgemm_kernel<<<g, 256, SM_GEMM>>>(ah, al, wh + WOFF_PROJ, wl + WOFF_PROJ, proj_b, x,
                                          out, nullptr, nullptr, 192, 180, 0, 0);
    }
    // 8. LN2 -> bf16 split (slot A)
    ln2_split_kernel<<<NPIX / 8, 256>>>(out, norm2_w, norm2_b, ah, al, NPIX);
    // 9. fc1 + GELU -> bf16 split (slot B)
    {
        dim3 g(3, NPIX / 128);
        hgemm_kernel<<<g, 256, SM_GEMM>>>(ah, al, wh + WOFF_FC1, wl + WOFF_FC1, fc1_b, nullptr,
                                          nullptr, (float*)(ah + SLOTB), (float*)(al + SLOTB), 192, 360, 384, 1);
    }
    // 10. fc2 + residual(x1) -> out
    {
        dim3 g(2, NPIX / 128);
        hgemm_kernel<<<g, 256, SM_GEMM>>>(ah + SLOTB, al + SLOTB, wh + WOFF_FC2, wl + WOFF_FC2, fc2_b, out,
                                          out, nullptr, nullptr, 384, 180, 0, 0);
    }
}